// round 8
// baseline (speedup 1.0000x reference)
#include <cuda_runtime.h>

// ---------------------------------------------------------------------------
// GAT layer, CSR-gather + tf32 tensor-core GEMM (3-term hi/lo split ~ fp32):
//   1. detect idx dtype, zero degree counters
//   2. counting sort edges by dst: histogram -> multi-block scan -> scatter
//   3. QKV GEMM (fused 3-in-1): W & A pre-converted to tf32 hi/lo in smem,
//      conflict-free LDS.64 fragment loads, mma.m16n8k8 (hi*hi+hi*lo+lo*hi)
//   4. aggregate: warp per dst; gather K/V[src], softmax accumulate in regs
//   5. output GEMM + bias + relu (same tf32 kernel)
// ---------------------------------------------------------------------------

#define MAXN 50048
#define MAXE 1600000
#define SCAN_BLK 1024
#define MAX_SBLKS 64

__device__ float g_Q[MAXN * 128];
__device__ float g_K[MAXN * 128];
__device__ float g_V[MAXN * 128];
__device__ float g_agg[MAXN * 128];
__device__ int   g_off[MAXN + 1];   // CSR row starts
__device__ int   g_cur[MAXN];       // scatter cursors; == row end after sort
__device__ int   g_srcs[MAXE];      // src ids sorted by dst
__device__ int   g_bsum[MAX_SBLKS]; // per-block sums for scan
__device__ int   g_idx64;           // 1 if edge_index is int64, 0 if int32

__device__ __forceinline__ int load_idx(const void* ei, long long pos, int M) {
    int v;
    if (g_idx64) v = (int)((const long long*)ei)[pos];
    else         v = ((const int*)ei)[pos];
    v = v < 0 ? 0 : (v >= M ? M - 1 : v);   // defensive clamp
    return v;
}

// ---------------------------------------------------------------------------
__global__ void detect_kernel(const unsigned* __restrict__ ei_u32) {
    if (threadIdx.x == 0 && blockIdx.x == 0) {
        int is64 = 1;
        for (int i = 0; i < 128; i++)
            if (ei_u32[2 * i + 1] != 0u) { is64 = 0; break; }
        g_idx64 = is64;
    }
}

__global__ void zero_deg(int M) {
    int t = blockIdx.x * blockDim.x + threadIdx.x;
    if (t < M) g_off[t] = 0;          // reuse g_off as degree counter
}

__global__ void hist_kernel(const void* __restrict__ ei, int E, int M) {
    int t = blockIdx.x * blockDim.x + threadIdx.x;
    if (t >= E) return;
    int dst = load_idx(ei, (long long)E + t, M);
    atomicAdd(&g_off[dst], 1);
}

// ---------------------------------------------------------------------------
// Multi-block exclusive scan of g_off[0..M) (degrees -> offsets).
// ---------------------------------------------------------------------------
__global__ void scan_partial(int M) {
    __shared__ int wsum[32];
    int tid  = threadIdx.x;
    int gi   = blockIdx.x * SCAN_BLK + tid;
    int lane = tid & 31;
    int wid  = tid >> 5;

    int v = (gi < M) ? g_off[gi] : 0;

    int x = v;
#pragma unroll
    for (int o = 1; o < 32; o <<= 1) {
        int y = __shfl_up_sync(0xFFFFFFFFu, x, o);
        if (lane >= o) x += y;
    }
    if (lane == 31) wsum[wid] = x;
    __syncthreads();

    if (wid == 0) {
        int w = wsum[lane];
#pragma unroll
        for (int o = 1; o < 32; o <<= 1) {
            int y = __shfl_up_sync(0xFFFFFFFFu, w, o);
            if (lane >= o) w += y;
        }
        wsum[lane] = w;
    }
    __syncthreads();

    int incl = x + (wid > 0 ? wsum[wid - 1] : 0);
    int excl = incl - v;
    if (gi < M) g_off[gi] = excl;
    if (tid == SCAN_BLK - 1) g_bsum[blockIdx.x] = incl;
}

__global__ void scan_bsums(int nb) {
    __shared__ int s[MAX_SBLKS];
    int lane = threadIdx.x;
    if (lane < MAX_SBLKS) s[lane] = (lane < nb) ? g_bsum[lane] : 0;
    __syncthreads();
    if (lane == 0) {
        int run = 0;
        for (int i = 0; i < nb; i++) { int t = s[i]; s[i] = run; run += t; }
        s[nb] = run;
    }
    __syncthreads();
    if (lane <= nb) g_bsum[lane] = s[lane];
}

__global__ void scan_add(int M) {
    int tid = threadIdx.x;
    int gi  = blockIdx.x * SCAN_BLK + tid;
    if (gi < M) {
        int o = g_off[gi] + g_bsum[blockIdx.x];
        g_off[gi] = o;
        g_cur[gi] = o;
    }
    if (gi == M) {
        int nb = (M + SCAN_BLK - 1) / SCAN_BLK;
        g_off[M] = g_bsum[nb];
    }
}

__global__ void scatter_kernel(const void* __restrict__ ei, int E, int M) {
    int t = blockIdx.x * blockDim.x + threadIdx.x;
    if (t >= E) return;
    int src = load_idx(ei, t, M);
    int dst = load_idx(ei, (long long)E + t, M);
    int pos = atomicAdd(&g_cur[dst], 1);
    g_srcs[pos] = src;
}

// ---------------------------------------------------------------------------
// tf32 tensor-core GEMM, 3-term hi/lo split (~fp32):
//   C[M,128] = A[M,128] @ W[128,128]^T + bias (+relu)
// 256 thr = 8 warps; warp w owns rows [w*16, w*16+16) x all 128 cols.
// W and A are pre-converted to interleaved tf32 (hi,lo) uint2 in smem:
//   Ws_hl[n][2k(+1)]  stride 264 (mod 32 == 8 -> conflict-free LDS.64)
//   As_hl[r][2k(+1)]  stride 72  (mod 32 == 8 -> conflict-free LDS.64)
// Inner loop: pure LDS.64 + mma.m16n8k8 (no cvt).
// blockIdx.y selects among up to 3 (W, bias, C) triples (fused QKV).
// ---------------------------------------------------------------------------
#define WHL_STRIDE 264
#define AHL_STRIDE 72
#define GEMM_SMEM ((128 * WHL_STRIDE + 128 * AHL_STRIDE) * 4)

__device__ __forceinline__ unsigned f2tf32(float x) {
    unsigned r;
    asm("cvt.rna.tf32.f32 %0, %1;" : "=r"(r) : "f"(x));
    return r;
}
__device__ __forceinline__ uint2 hl_split(float x) {
    uint2 r;
    r.x = f2tf32(x);
    r.y = f2tf32(x - __uint_as_float(r.x));
    return r;
}

__device__ __forceinline__ void mma_tf32(float* d,
                                         unsigned a0, unsigned a1,
                                         unsigned a2, unsigned a3,
                                         unsigned b0, unsigned b1) {
    asm("mma.sync.aligned.m16n8k8.row.col.f32.tf32.tf32.f32 "
        "{%0,%1,%2,%3}, {%4,%5,%6,%7}, {%8,%9}, {%0,%1,%2,%3};"
        : "+f"(d[0]), "+f"(d[1]), "+f"(d[2]), "+f"(d[3])
        : "r"(a0), "r"(a1), "r"(a2), "r"(a3), "r"(b0), "r"(b1));
}

__global__ __launch_bounds__(256, 1)
void gemm_tf32_kernel(const float* __restrict__ A, int M,
                      const float* __restrict__ Wa, const float* __restrict__ Wb,
                      const float* __restrict__ Wc,
                      const float* __restrict__ ba, const float* __restrict__ bb,
                      const float* __restrict__ bc,
                      float* __restrict__ Ca, float* __restrict__ Cb,
                      float* __restrict__ Cc,
                      int relu)
{
    extern __shared__ unsigned smem_u[];
    unsigned* Ws = smem_u;                        // [128][WHL_STRIDE]
    unsigned* As = smem_u + 128 * WHL_STRIDE;     // [128][AHL_STRIDE]

    const float* W;
    const float* bias;
    float*       C;
    if (blockIdx.y == 0)      { W = Wa; bias = ba; C = Ca; }
    else if (blockIdx.y == 1) { W = Wb; bias = bb; C = Cb; }
    else                      { W = Wc; bias = bc; C = Cc; }

    int tid  = threadIdx.x;
    int wid  = tid >> 5;
    int lane = tid & 31;
    int g    = lane >> 2;      // group id 0..7
    int c    = lane & 3;       // thread-in-group 0..3
    int m0   = blockIdx.x * 128;

    // stage W (128x128) as tf32 hi/lo pairs: 16 float4 per thread
#pragma unroll
    for (int i = 0; i < 16; i++) {
        int i4  = tid + i * 256;        // 0..4095
        int row = i4 >> 5;              // 0..127
        int c4  = (i4 & 31) * 4;        // 0..124
        float4 w = *(const float4*)(W + (size_t)row * 128 + c4);
        uint2* p = (uint2*)(Ws + row * WHL_STRIDE + 2 * c4);
        p[0] = hl_split(w.x);
        p[1] = hl_split(w.y);
        p[2] = hl_split(w.z);
        p[3] = hl_split(w.w);
    }

    float acc[16][4];
#pragma unroll
    for (int t = 0; t < 16; t++)
#pragma unroll
        for (int j = 0; j < 4; j++) acc[t][j] = 0.f;

    int r0 = wid * 16 + g;     // warp-local A rows r0, r0+8

    for (int slab = 0; slab < 4; slab++) {
        __syncthreads();
        // stage A slab rows 0..127, k in [slab*32, slab*32+32), as hi/lo pairs
#pragma unroll
        for (int i = 0; i < 4; i++) {
            int idx = tid + i * 256;    // 0..1023 float4 slots
            int row = idx >> 3;         // 0..127
            int kq  = idx & 7;          // 0..7
            float4 v = make_float4(0.f, 0.f, 0.f, 0.f);
            int m = m0 + row;
            if (m < M)
                v = *(const float4*)(A + (size_t)m * 128 + slab * 32 + kq * 4);
            uint2* p = (uint2*)(As + row * AHL_STRIDE + 2 * (kq * 4));
            p[0] = hl_split(v.x);
            p[1] = hl_split(v.y);
            p[2] = hl_split(v.z);
            p[3] = hl_split(v.w);
        }
        __syncthreads();

#pragma unroll
        for (int kk = 0; kk < 4; kk++) {
            int kc = kk * 8 + c;   // k within slab for this thread
            uint2 a0 = *(const uint2*)(As + r0 * AHL_STRIDE + 2 * kc);
            uint2 a1 = *(const uint2*)(As + (r0 + 8) * AHL_STRIDE + 2 * kc);
            uint2 a2 = *(const uint2*)(As + r0 * AHL_STRIDE + 2 * (kc + 4));
            uint2 a3 = *(const uint2*)(As + (r0 + 8) * AHL_STRIDE + 2 * (kc + 4));

            int kg = slab * 32 + kk * 8;   // global k base
#pragma unroll
            for (int nt = 0; nt < 16; nt++) {
                int n = nt * 8 + g;
                uint2 b0 = *(const uint2*)(Ws + n * WHL_STRIDE + 2 * (kg + c));
                uint2 b1 = *(const uint2*)(Ws + n * WHL_STRIDE + 2 * (kg + c + 4));

                mma_tf32(acc[nt], a0.x, a1.x, a2.x, a3.x, b0.y, b1.y);  // hi*lo
                mma_tf32(acc[nt], a0.y, a1.y, a2.y, a3.y, b0.x, b1.x);  // lo*hi
                mma_tf32(acc[nt], a0.x, a1.x, a2.x, a3.x, b0.x, b1.x);  // hi*hi
            }
        }
    }

    // epilogue: bias + optional relu; rows m0+r0, m0+r0+8; cols nt*8+2c(+1)
    int mA = m0 + r0;
    int mB = mA + 8;
#pragma unroll
    for (int nt = 0; nt < 16; nt++) {
        int n = nt * 8 + 2 * c;
        float bx = bias[n], by = bias[n + 1];
        float2 oA = make_float2(acc[nt][0] + bx, acc[nt][1] + by);
        float2 oB = make_float2(acc[nt][2] + bx, acc[nt][3] + by);
        if (relu) {
            oA.x = fmaxf(oA.x, 0.f); oA.y = fmaxf(oA.y, 0.f);
            oB.x = fmaxf(oB.x, 0.f); oB.y = fmaxf(oB.y, 0.f);
        }
        if (mA < M) *(float2*)(C + (size_t)mA * 128 + n) = oA;
        if (mB < M) *(float2*)(C + (size_t)mB * 128 + n) = oB;
    }
}

// ---------------------------------------------------------------------------
// Warp per dst node: softmax-weighted aggregation of V[src] over CSR edges.
// ---------------------------------------------------------------------------
__device__ __forceinline__ void edge_step(int sj, const float4& q,
                                          float4& acc, float& ssum, int lane)
{
    float4 k = ((const float4*)(g_K + (size_t)sj * 128))[lane];
    float4 v = ((const float4*)(g_V + (size_t)sj * 128))[lane];
    float part = q.x * k.x + q.y * k.y + q.z * k.z + q.w * k.w;
    part += __shfl_xor_sync(0xFFFFFFFFu, part, 1);
    part += __shfl_xor_sync(0xFFFFFFFFu, part, 2);
    part += __shfl_xor_sync(0xFFFFFFFFu, part, 4);
    float p = __expf(part * 0.17677669529663687f);
    acc.x = fmaf(p, v.x, acc.x);
    acc.y = fmaf(p, v.y, acc.y);
    acc.z = fmaf(p, v.z, acc.z);
    acc.w = fmaf(p, v.w, acc.w);
    ssum += p;
}

__global__ __launch_bounds__(256)
void aggregate_kernel(int M)
{
    int w    = (int)(((long long)blockIdx.x * blockDim.x + threadIdx.x) >> 5);
    int lane = threadIdx.x & 31;
    if (w >= M) return;

    int start = g_off[w];
    int end   = g_cur[w];    // == g_off[w+1] after scatter

    float4 q = ((const float4*)(g_Q + (size_t)w * 128))[lane];
    float4 acc = make_float4(0.f, 0.f, 0.f, 0.f);
    float ssum = 0.f;

    int i = start;
    for (; i + 32 <= end; i += 32) {
        int s = g_srcs[i + lane];
#pragma unroll 4
        for (int j = 0; j < 32; j++) {
            int sj = __shfl_sync(0xFFFFFFFFu, s, j);
            edge_step(sj, q, acc, ssum, lane);
        }
    }
    if (i < end) {
        int rem = end - i;
        int s = (lane < rem) ? g_srcs[i + lane] : 0;
        for (int j = 0; j < rem; j++) {
            int sj = __shfl_sync(0xFFFFFFFFu, s, j);
            edge_step(sj, q, acc, ssum, lane);
        }
    }

    float inv = 1.f / (ssum + 1e-8f);
    float4 o = make_float4(acc.x * inv, acc.y * inv, acc.z * inv, acc.w * inv);
    ((float4*)(g_agg + (size_t)w * 128))[lane] = o;
}

// ---------------------------------------------------------------------------
extern "C" void kernel_launch(void* const* d_in, const int* in_sizes, int n_in,
                              void* d_out, int out_size)
{
    const float* x  = (const float*)d_in[0];
    const void*  ei = d_in[1];
    const float* Wq = (const float*)d_in[2];
    const float* bq = (const float*)d_in[3];
    const float* Wk = (const float*)d_in[4];
    const float* bk = (const float*)d_in[5];
    const float* Wv = (const float*)d_in[6];
    const float* bv = (const float*)d_in[7];
    const float* Wo = (const float*)d_in[8];
    const float* bo = (const float*)d_in[9];
    float*       out = (float*)d_out;

    int M = in_sizes[0] / 128;   // nodes
    int E = in_sizes[1] / 2;     // edges

    float *pQ, *pK, *pV, *pAgg;
    cudaGetSymbolAddress((void**)&pQ,   g_Q);
    cudaGetSymbolAddress((void**)&pK,   g_K);
    cudaGetSymbolAddress((void**)&pV,   g_V);
    cudaGetSymbolAddress((void**)&pAgg, g_agg);

    cudaFuncSetAttribute(gemm_tf32_kernel,
                         cudaFuncAttributeMaxDynamicSharedMemorySize, GEMM_SMEM);

    int nb = (M + SCAN_BLK - 1) / SCAN_BLK;   // 49 for M=50000

    detect_kernel<<<1, 32>>>((const unsigned*)ei);
    zero_deg<<<(M + 255) / 256, 256>>>(M);
    hist_kernel<<<(E + 255) / 256, 256>>>(ei, E, M);
    scan_partial<<<nb, SCAN_BLK>>>(M);
    scan_bsums<<<1, MAX_SBLKS>>>(nb);
    scan_add<<<nb + 1, SCAN_BLK>>>(M);
    scatter_kernel<<<(E + 255) / 256, 256>>>(ei, E, M);

    dim3 gqkv((M + 127) / 128, 3);
    gemm_tf32_kernel<<<gqkv, 256, GEMM_SMEM>>>(x, M, Wq, Wk, Wv, bq, bk, bv,
                                               pQ, pK, pV, 0);

    long long wt = (long long)M * 32;
    aggregate_kernel<<<(int)((wt + 255) / 256), 256>>>(M);

    dim3 gout((M + 127) / 128, 1);
    gemm_tf32_kernel<<<gout, 256, GEMM_SMEM>>>(pAgg, M, Wo, Wo, Wo, bo, bo, bo,
                                               out, out, out, 1);
}

// round 9
// speedup vs baseline: 1.1326x; 1.1326x over previous
#include <cuda_runtime.h>

// ---------------------------------------------------------------------------
// GAT layer, CSR-gather + tf32 tensor-core GEMM (3-term hi/lo split ~ fp32):
//   1. detect idx dtype, zero degree counters
//   2. counting sort edges by dst: histogram -> multi-block scan -> scatter
//   3. QKV GEMM (fused 3-in-1): N-split blocks (128x64 tile); W half
//      pre-converted once to tf32 hi/lo uint2 smem (conflict-free LDS.64);
//      A fp32 smem, converted in-loop; mma.m16n8k8 (hi*hi+hi*lo+lo*hi)
//   4. aggregate: warp per dst; gather K/V[src], softmax accumulate in regs
//   5. output GEMM + bias + relu (same tf32 kernel)
// ---------------------------------------------------------------------------

#define MAXN 50048
#define MAXE 1600000
#define SCAN_BLK 1024
#define MAX_SBLKS 64

__device__ float g_Q[MAXN * 128];
__device__ float g_K[MAXN * 128];
__device__ float g_V[MAXN * 128];
__device__ float g_agg[MAXN * 128];
__device__ int   g_off[MAXN + 1];   // CSR row starts
__device__ int   g_cur[MAXN];       // scatter cursors; == row end after sort
__device__ int   g_srcs[MAXE];      // src ids sorted by dst
__device__ int   g_bsum[MAX_SBLKS]; // per-block sums for scan
__device__ int   g_idx64;           // 1 if edge_index is int64, 0 if int32

__device__ __forceinline__ int load_idx(const void* ei, long long pos, int M) {
    int v;
    if (g_idx64) v = (int)((const long long*)ei)[pos];
    else         v = ((const int*)ei)[pos];
    v = v < 0 ? 0 : (v >= M ? M - 1 : v);   // defensive clamp
    return v;
}

// ---------------------------------------------------------------------------
__global__ void detect_kernel(const unsigned* __restrict__ ei_u32) {
    if (threadIdx.x == 0 && blockIdx.x == 0) {
        int is64 = 1;
        for (int i = 0; i < 128; i++)
            if (ei_u32[2 * i + 1] != 0u) { is64 = 0; break; }
        g_idx64 = is64;
    }
}

__global__ void zero_deg(int M) {
    int t = blockIdx.x * blockDim.x + threadIdx.x;
    if (t < M) g_off[t] = 0;          // reuse g_off as degree counter
}

__global__ void hist_kernel(const void* __restrict__ ei, int E, int M) {
    int t = blockIdx.x * blockDim.x + threadIdx.x;
    if (t >= E) return;
    int dst = load_idx(ei, (long long)E + t, M);
    atomicAdd(&g_off[dst], 1);
}

// ---------------------------------------------------------------------------
// Multi-block exclusive scan of g_off[0..M) (degrees -> offsets).
// ---------------------------------------------------------------------------
__global__ void scan_partial(int M) {
    __shared__ int wsum[32];
    int tid  = threadIdx.x;
    int gi   = blockIdx.x * SCAN_BLK + tid;
    int lane = tid & 31;
    int wid  = tid >> 5;

    int v = (gi < M) ? g_off[gi] : 0;

    int x = v;
#pragma unroll
    for (int o = 1; o < 32; o <<= 1) {
        int y = __shfl_up_sync(0xFFFFFFFFu, x, o);
        if (lane >= o) x += y;
    }
    if (lane == 31) wsum[wid] = x;
    __syncthreads();

    if (wid == 0) {
        int w = wsum[lane];
#pragma unroll
        for (int o = 1; o < 32; o <<= 1) {
            int y = __shfl_up_sync(0xFFFFFFFFu, w, o);
            if (lane >= o) w += y;
        }
        wsum[lane] = w;
    }
    __syncthreads();

    int incl = x + (wid > 0 ? wsum[wid - 1] : 0);
    int excl = incl - v;
    if (gi < M) g_off[gi] = excl;
    if (tid == SCAN_BLK - 1) g_bsum[blockIdx.x] = incl;
}

__global__ void scan_bsums(int nb) {
    __shared__ int s[MAX_SBLKS];
    int lane = threadIdx.x;
    if (lane < MAX_SBLKS) s[lane] = (lane < nb) ? g_bsum[lane] : 0;
    __syncthreads();
    if (lane == 0) {
        int run = 0;
        for (int i = 0; i < nb; i++) { int t = s[i]; s[i] = run; run += t; }
        s[nb] = run;
    }
    __syncthreads();
    if (lane <= nb) g_bsum[lane] = s[lane];
}

__global__ void scan_add(int M) {
    int tid = threadIdx.x;
    int gi  = blockIdx.x * SCAN_BLK + tid;
    if (gi < M) {
        int o = g_off[gi] + g_bsum[blockIdx.x];
        g_off[gi] = o;
        g_cur[gi] = o;
    }
    if (gi == M) {
        int nb = (M + SCAN_BLK - 1) / SCAN_BLK;
        g_off[M] = g_bsum[nb];
    }
}

__global__ void scatter_kernel(const void* __restrict__ ei, int E, int M) {
    int t = blockIdx.x * blockDim.x + threadIdx.x;
    if (t >= E) return;
    int src = load_idx(ei, t, M);
    int dst = load_idx(ei, (long long)E + t, M);
    int pos = atomicAdd(&g_cur[dst], 1);
    g_srcs[pos] = src;
}

// ---------------------------------------------------------------------------
// tf32 tensor-core GEMM, 3-term hi/lo split (~fp32):
//   C tile = A[128 rows, 128k] @ Whalf[64, 128]^T + bias (+relu)
// 256 thr = 8 warps; warp w owns rows [w*16, w*16+16) x 64 cols (8 m16n8 accs).
// W half pre-converted ONCE to interleaved tf32 (hi,lo) uint2:
//   Ws[n][2k(+1)], stride 264 words -> 8B-bank = 4g+c, conflict-free LDS.64.
// A fp32 smem slabs (stride 36 -> bank 4g+c, conflict-free), cvt in loop.
// blockIdx.y: bit0 = n-half (0/1), bits>=1 = matrix select (QKV fusion).
// ---------------------------------------------------------------------------
#define WHL_STRIDE 264
#define AS_STRIDE 36
#define GEMM_SMEM ((64 * WHL_STRIDE + 128 * AS_STRIDE) * 4)

__device__ __forceinline__ unsigned f2tf32(float x) {
    unsigned r;
    asm("cvt.rna.tf32.f32 %0, %1;" : "=r"(r) : "f"(x));
    return r;
}
__device__ __forceinline__ uint2 hl_split(float x) {
    uint2 r;
    r.x = f2tf32(x);
    r.y = f2tf32(x - __uint_as_float(r.x));
    return r;
}

__device__ __forceinline__ void mma_tf32(float* d,
                                         unsigned a0, unsigned a1,
                                         unsigned a2, unsigned a3,
                                         unsigned b0, unsigned b1) {
    asm("mma.sync.aligned.m16n8k8.row.col.f32.tf32.tf32.f32 "
        "{%0,%1,%2,%3}, {%4,%5,%6,%7}, {%8,%9}, {%0,%1,%2,%3};"
        : "+f"(d[0]), "+f"(d[1]), "+f"(d[2]), "+f"(d[3])
        : "r"(a0), "r"(a1), "r"(a2), "r"(a3), "r"(b0), "r"(b1));
}

__global__ __launch_bounds__(256, 2)
void gemm_tf32_kernel(const float* __restrict__ A, int M,
                      const float* __restrict__ Wa, const float* __restrict__ Wb,
                      const float* __restrict__ Wc,
                      const float* __restrict__ ba, const float* __restrict__ bb,
                      const float* __restrict__ bc,
                      float* __restrict__ Ca, float* __restrict__ Cb,
                      float* __restrict__ Cc,
                      int relu)
{
    extern __shared__ unsigned smem_u[];
    unsigned* Ws = smem_u;                            // [64][WHL_STRIDE]
    float*    As = (float*)(smem_u + 64 * WHL_STRIDE); // [128][AS_STRIDE]

    int mat  = blockIdx.y >> 1;
    int n0   = (blockIdx.y & 1) * 64;    // n-half offset

    const float* W;
    const float* bias;
    float*       C;
    if (mat == 0)      { W = Wa; bias = ba; C = Ca; }
    else if (mat == 1) { W = Wb; bias = bb; C = Cb; }
    else               { W = Wc; bias = bc; C = Cc; }

    int tid  = threadIdx.x;
    int wid  = tid >> 5;
    int lane = tid & 31;
    int g    = lane >> 2;      // group id 0..7
    int c    = lane & 3;       // thread-in-group 0..3
    int m0   = blockIdx.x * 128;

    // stage W half (rows n0..n0+63 of W) as tf32 hi/lo pairs: 8 float4/thread
#pragma unroll
    for (int i = 0; i < 8; i++) {
        int i4  = tid + i * 256;        // 0..2047
        int row = i4 >> 5;              // 0..63  (local n)
        int c4  = (i4 & 31) * 4;        // k: 0..124
        float4 w = *(const float4*)(W + (size_t)(n0 + row) * 128 + c4);
        uint2* p = (uint2*)(Ws + row * WHL_STRIDE + 2 * c4);
        p[0] = hl_split(w.x);
        p[1] = hl_split(w.y);
        p[2] = hl_split(w.z);
        p[3] = hl_split(w.w);
    }

    float acc[8][4];
#pragma unroll
    for (int t = 0; t < 8; t++)
#pragma unroll
        for (int j = 0; j < 4; j++) acc[t][j] = 0.f;

    int r0 = wid * 16 + g;     // warp-local A rows r0, r0+8

    for (int slab = 0; slab < 4; slab++) {
        __syncthreads();
        // stage A slab rows 0..127, k in [slab*32, slab*32+32) (fp32)
#pragma unroll
        for (int i = 0; i < 4; i++) {
            int idx = tid + i * 256;    // 0..1023 float4 slots
            int row = idx >> 3;         // 0..127
            int kq  = idx & 7;          // 0..7
            float4 v = make_float4(0.f, 0.f, 0.f, 0.f);
            int m = m0 + row;
            if (m < M)
                v = *(const float4*)(A + (size_t)m * 128 + slab * 32 + kq * 4);
            float* p = As + row * AS_STRIDE + kq * 4;
            p[0] = v.x; p[1] = v.y; p[2] = v.z; p[3] = v.w;
        }
        __syncthreads();

#pragma unroll
        for (int kk = 0; kk < 4; kk++) {
            int kc = kk * 8 + c;   // k within slab for this thread
            uint2 a0 = hl_split(As[r0 * AS_STRIDE + kc]);
            uint2 a1 = hl_split(As[(r0 + 8) * AS_STRIDE + kc]);
            uint2 a2 = hl_split(As[r0 * AS_STRIDE + kc + 4]);
            uint2 a3 = hl_split(As[(r0 + 8) * AS_STRIDE + kc + 4]);

            int kg = slab * 32 + kk * 8;   // global k base
#pragma unroll
            for (int nt = 0; nt < 8; nt++) {
                int n = nt * 8 + g;        // local n in half
                uint2 b0 = *(const uint2*)(Ws + n * WHL_STRIDE + 2 * (kg + c));
                uint2 b1 = *(const uint2*)(Ws + n * WHL_STRIDE + 2 * (kg + c + 4));

                mma_tf32(acc[nt], a0.x, a1.x, a2.x, a3.x, b0.y, b1.y);  // hi*lo
                mma_tf32(acc[nt], a0.y, a1.y, a2.y, a3.y, b0.x, b1.x);  // lo*hi
                mma_tf32(acc[nt], a0.x, a1.x, a2.x, a3.x, b0.x, b1.x);  // hi*hi
            }
        }
    }

    // epilogue: bias + optional relu; rows m0+r0, m0+r0+8; cols n0+nt*8+2c(+1)
    int mA = m0 + r0;
    int mB = mA + 8;
#pragma unroll
    for (int nt = 0; nt < 8; nt++) {
        int n = n0 + nt * 8 + 2 * c;
        float bx = bias[n], by = bias[n + 1];
        float2 oA = make_float2(acc[nt][0] + bx, acc[nt][1] + by);
        float2 oB = make_float2(acc[nt][2] + bx, acc[nt][3] + by);
        if (relu) {
            oA.x = fmaxf(oA.x, 0.f); oA.y = fmaxf(oA.y, 0.f);
            oB.x = fmaxf(oB.x, 0.f); oB.y = fmaxf(oB.y, 0.f);
        }
        if (mA < M) *(float2*)(C + (size_t)mA * 128 + n) = oA;
        if (mB < M) *(float2*)(C + (size_t)mB * 128 + n) = oB;
    }
}

// ---------------------------------------------------------------------------
// Warp per dst node: softmax-weighted aggregation of V[src] over CSR edges.
// ---------------------------------------------------------------------------
__device__ __forceinline__ void edge_step(int sj, const float4& q,
                                          float4& acc, float& ssum, int lane)
{
    float4 k = ((const float4*)(g_K + (size_t)sj * 128))[lane];
    float4 v = ((const float4*)(g_V + (size_t)sj * 128))[lane];
    float part = q.x * k.x + q.y * k.y + q.z * k.z + q.w * k.w;
    part += __shfl_xor_sync(0xFFFFFFFFu, part, 1);
    part += __shfl_xor_sync(0xFFFFFFFFu, part, 2);
    part += __shfl_xor_sync(0xFFFFFFFFu, part, 4);
    float p = __expf(part * 0.17677669529663687f);
    acc.x = fmaf(p, v.x, acc.x);
    acc.y = fmaf(p, v.y, acc.y);
    acc.z = fmaf(p, v.z, acc.z);
    acc.w = fmaf(p, v.w, acc.w);
    ssum += p;
}

__global__ __launch_bounds__(256)
void aggregate_kernel(int M)
{
    int w    = (int)(((long long)blockIdx.x * blockDim.x + threadIdx.x) >> 5);
    int lane = threadIdx.x & 31;
    if (w >= M) return;

    int start = g_off[w];
    int end   = g_cur[w];    // == g_off[w+1] after scatter

    float4 q = ((const float4*)(g_Q + (size_t)w * 128))[lane];
    float4 acc = make_float4(0.f, 0.f, 0.f, 0.f);
    float ssum = 0.f;

    int i = start;
    for (; i + 32 <= end; i += 32) {
        int s = g_srcs[i + lane];
#pragma unroll 4
        for (int j = 0; j < 32; j++) {
            int sj = __shfl_sync(0xFFFFFFFFu, s, j);
            edge_step(sj, q, acc, ssum, lane);
        }
    }
    if (i < end) {
        int rem = end - i;
        int s = (lane < rem) ? g_srcs[i + lane] : 0;
        for (int j = 0; j < rem; j++) {
            int sj = __shfl_sync(0xFFFFFFFFu, s, j);
            edge_step(sj, q, acc, ssum, lane);
        }
    }

    float inv = 1.f / (ssum + 1e-8f);
    float4 o = make_float4(acc.x * inv, acc.y * inv, acc.z * inv, acc.w * inv);
    ((float4*)(g_agg + (size_t)w * 128))[lane] = o;
}

// ---------------------------------------------------------------------------
extern "C" void kernel_launch(void* const* d_in, const int* in_sizes, int n_in,
                              void* d_out, int out_size)
{
    const float* x  = (const float*)d_in[0];
    const void*  ei = d_in[1];
    const float* Wq = (const float*)d_in[2];
    const float* bq = (const float*)d_in[3];
    const float* Wk = (const float*)d_in[4];
    const float* bk = (const float*)d_in[5];
    const float* Wv = (const float*)d_in[6];
    const float* bv = (const float*)d_in[7];
    const float* Wo = (const float*)d_in[8];
    const float* bo = (const float*)d_in[9];
    float*       out = (float*)d_out;

    int M = in_sizes[0] / 128;   // nodes
    int E = in_sizes[1] / 2;     // edges

    float *pQ, *pK, *pV, *pAgg;
    cudaGetSymbolAddress((void**)&pQ,   g_Q);
    cudaGetSymbolAddress((void**)&pK,   g_K);
    cudaGetSymbolAddress((void**)&pV,   g_V);
    cudaGetSymbolAddress((void**)&pAgg, g_agg);

    cudaFuncSetAttribute(gemm_tf32_kernel,
                         cudaFuncAttributeMaxDynamicSharedMemorySize, GEMM_SMEM);

    int nb = (M + SCAN_BLK - 1) / SCAN_BLK;   // 49 for M=50000

    detect_kernel<<<1, 32>>>((const unsigned*)ei);
    zero_deg<<<(M + 255) / 256, 256>>>(M);
    hist_kernel<<<(E + 255) / 256, 256>>>(ei, E, M);
    scan_partial<<<nb, SCAN_BLK>>>(M);
    scan_bsums<<<1, MAX_SBLKS>>>(nb);
    scan_add<<<nb + 1, SCAN_BLK>>>(M);
    scatter_kernel<<<(E + 255) / 256, 256>>>(ei, E, M);

    dim3 gqkv((M + 127) / 128, 6);   // 3 matrices x 2 n-halves
    gemm_tf32_kernel<<<gqkv, 256, GEMM_SMEM>>>(x, M, Wq, Wk, Wv, bq, bk, bv,
                                               pQ, pK, pV, 0);

    long long wt = (long long)M * 32;
    aggregate_kernel<<<(int)((wt + 255) / 256), 256>>>(M);

    dim3 gout((M + 127) / 128, 2);   // 1 matrix x 2 n-halves
    gemm_tf32_kernel<<<gout, 256, GEMM_SMEM>>>(pAgg, M, Wo, Wo, Wo, bo, bo, bo,
                                               out, out, out, 1);
}

// round 10
// speedup vs baseline: 1.1736x; 1.0362x over previous
#include <cuda_runtime.h>

// ---------------------------------------------------------------------------
// GAT layer, CSR-gather + tf32 tensor-core GEMM (3-term hi/lo split ~ fp32),
// two-stream overlap:
//   stream A (legacy): QKV GEMM  (only needs x, W*)
//   stream B:          CSR build (detect -> zero -> hist -> scan -> scatter)
//   join -> aggregate (warp per dst, register softmax) -> output GEMM + relu
// ---------------------------------------------------------------------------

#define MAXN 50048
#define MAXE 1600000
#define SCAN_BLK 1024
#define MAX_SBLKS 64

__device__ float g_Q[MAXN * 128];
__device__ float g_K[MAXN * 128];
__device__ float g_V[MAXN * 128];
__device__ float g_agg[MAXN * 128];
__device__ int   g_off[MAXN + 1];   // CSR row starts
__device__ int   g_cur[MAXN];       // scatter cursors; == row end after sort
__device__ int   g_srcs[MAXE];      // src ids sorted by dst
__device__ int   g_bsum[MAX_SBLKS]; // per-block sums for scan
__device__ int   g_idx64;           // 1 if edge_index is int64, 0 if int32

__device__ __forceinline__ int load_idx(const void* ei, long long pos, int M) {
    int v;
    if (g_idx64) v = (int)((const long long*)ei)[pos];
    else         v = ((const int*)ei)[pos];
    v = v < 0 ? 0 : (v >= M ? M - 1 : v);   // defensive clamp
    return v;
}

// ---------------------------------------------------------------------------
__global__ void detect_kernel(const unsigned* __restrict__ ei_u32) {
    if (threadIdx.x == 0 && blockIdx.x == 0) {
        int is64 = 1;
        for (int i = 0; i < 128; i++)
            if (ei_u32[2 * i + 1] != 0u) { is64 = 0; break; }
        g_idx64 = is64;
    }
}

__global__ void zero_deg(int M) {
    int t = blockIdx.x * blockDim.x + threadIdx.x;
    if (t < M) g_off[t] = 0;          // reuse g_off as degree counter
}

__global__ void hist_kernel(const void* __restrict__ ei, int E, int M) {
    int t = blockIdx.x * blockDim.x + threadIdx.x;
    if (t >= E) return;
    int dst = load_idx(ei, (long long)E + t, M);
    atomicAdd(&g_off[dst], 1);
}

// ---------------------------------------------------------------------------
// Multi-block exclusive scan of g_off[0..M) (degrees -> offsets).
// ---------------------------------------------------------------------------
__global__ void scan_partial(int M) {
    __shared__ int wsum[32];
    int tid  = threadIdx.x;
    int gi   = blockIdx.x * SCAN_BLK + tid;
    int lane = tid & 31;
    int wid  = tid >> 5;

    int v = (gi < M) ? g_off[gi] : 0;

    int x = v;
#pragma unroll
    for (int o = 1; o < 32; o <<= 1) {
        int y = __shfl_up_sync(0xFFFFFFFFu, x, o);
        if (lane >= o) x += y;
    }
    if (lane == 31) wsum[wid] = x;
    __syncthreads();

    if (wid == 0) {
        int w = wsum[lane];
#pragma unroll
        for (int o = 1; o < 32; o <<= 1) {
            int y = __shfl_up_sync(0xFFFFFFFFu, w, o);
            if (lane >= o) w += y;
        }
        wsum[lane] = w;
    }
    __syncthreads();

    int incl = x + (wid > 0 ? wsum[wid - 1] : 0);
    int excl = incl - v;
    if (gi < M) g_off[gi] = excl;
    if (tid == SCAN_BLK - 1) g_bsum[blockIdx.x] = incl;
}

__global__ void scan_bsums(int nb) {
    __shared__ int s[MAX_SBLKS];
    int lane = threadIdx.x;
    if (lane < MAX_SBLKS) s[lane] = (lane < nb) ? g_bsum[lane] : 0;
    __syncthreads();
    if (lane == 0) {
        int run = 0;
        for (int i = 0; i < nb; i++) { int t = s[i]; s[i] = run; run += t; }
        s[nb] = run;
    }
    __syncthreads();
    if (lane <= nb) g_bsum[lane] = s[lane];
}

__global__ void scan_add(int M) {
    int tid = threadIdx.x;
    int gi  = blockIdx.x * SCAN_BLK + tid;
    if (gi < M) {
        int o = g_off[gi] + g_bsum[blockIdx.x];
        g_off[gi] = o;
        g_cur[gi] = o;
    }
    if (gi == M) {
        int nb = (M + SCAN_BLK - 1) / SCAN_BLK;
        g_off[M] = g_bsum[nb];
    }
}

__global__ void scatter_kernel(const void* __restrict__ ei, int E, int M) {
    int t = blockIdx.x * blockDim.x + threadIdx.x;
    if (t >= E) return;
    int src = load_idx(ei, t, M);
    int dst = load_idx(ei, (long long)E + t, M);
    int pos = atomicAdd(&g_cur[dst], 1);
    g_srcs[pos] = src;
}

// ---------------------------------------------------------------------------
// tf32 tensor-core GEMM, 3-term hi/lo split (~fp32):
//   C tile = A[128 rows, 128k] @ Whalf[64, 128]^T + bias (+relu)
// 256 thr = 8 warps; warp w owns rows [w*16, w*16+16) x 64 cols (8 m16n8 accs).
// W half pre-converted ONCE to interleaved tf32 (hi,lo) uint2 (stride 264:
// conflict-free LDS.64); A fp32 smem (stride 36: conflict-free), cvt in loop.
// blockIdx.y: bit0 = n-half (0/1), bits>=1 = matrix select (QKV fusion).
// ---------------------------------------------------------------------------
#define WHL_STRIDE 264
#define AS_STRIDE 36
#define GEMM_SMEM ((64 * WHL_STRIDE + 128 * AS_STRIDE) * 4)

__device__ __forceinline__ unsigned f2tf32(float x) {
    unsigned r;
    asm("cvt.rna.tf32.f32 %0, %1;" : "=r"(r) : "f"(x));
    return r;
}
__device__ __forceinline__ uint2 hl_split(float x) {
    uint2 r;
    r.x = f2tf32(x);
    r.y = f2tf32(x - __uint_as_float(r.x));
    return r;
}

__device__ __forceinline__ void mma_tf32(float* d,
                                         unsigned a0, unsigned a1,
                                         unsigned a2, unsigned a3,
                                         unsigned b0, unsigned b1) {
    asm("mma.sync.aligned.m16n8k8.row.col.f32.tf32.tf32.f32 "
        "{%0,%1,%2,%3}, {%4,%5,%6,%7}, {%8,%9}, {%0,%1,%2,%3};"
        : "+f"(d[0]), "+f"(d[1]), "+f"(d[2]), "+f"(d[3])
        : "r"(a0), "r"(a1), "r"(a2), "r"(a3), "r"(b0), "r"(b1));
}

__global__ __launch_bounds__(256, 2)
void gemm_tf32_kernel(const float* __restrict__ A, int M,
                      const float* __restrict__ Wa, const float* __restrict__ Wb,
                      const float* __restrict__ Wc,
                      const float* __restrict__ ba, const float* __restrict__ bb,
                      const float* __restrict__ bc,
                      float* __restrict__ Ca, float* __restrict__ Cb,
                      float* __restrict__ Cc,
                      int relu)
{
    extern __shared__ unsigned smem_u[];
    unsigned* Ws = smem_u;                             // [64][WHL_STRIDE]
    float*    As = (float*)(smem_u + 64 * WHL_STRIDE); // [128][AS_STRIDE]

    int mat  = blockIdx.y >> 1;
    int n0   = (blockIdx.y & 1) * 64;    // n-half offset

    const float* W;
    const float* bias;
    float*       C;
    if (mat == 0)      { W = Wa; bias = ba; C = Ca; }
    else if (mat == 1) { W = Wb; bias = bb; C = Cb; }
    else               { W = Wc; bias = bc; C = Cc; }

    int tid  = threadIdx.x;
    int wid  = tid >> 5;
    int lane = tid & 31;
    int g    = lane >> 2;      // group id 0..7
    int c    = lane & 3;       // thread-in-group 0..3
    int m0   = blockIdx.x * 128;

    // stage W half (rows n0..n0+63 of W) as tf32 hi/lo pairs: 8 float4/thread
#pragma unroll
    for (int i = 0; i < 8; i++) {
        int i4  = tid + i * 256;        // 0..2047
        int row = i4 >> 5;              // 0..63  (local n)
        int c4  = (i4 & 31) * 4;        // k: 0..124
        float4 w = *(const float4*)(W + (size_t)(n0 + row) * 128 + c4);
        uint2* p = (uint2*)(Ws + row * WHL_STRIDE + 2 * c4);
        p[0] = hl_split(w.x);
        p[1] = hl_split(w.y);
        p[2] = hl_split(w.z);
        p[3] = hl_split(w.w);
    }

    float acc[8][4];
#pragma unroll
    for (int t = 0; t < 8; t++)
#pragma unroll
        for (int j = 0; j < 4; j++) acc[t][j] = 0.f;

    int r0 = wid * 16 + g;     // warp-local A rows r0, r0+8

    for (int slab = 0; slab < 4; slab++) {
        __syncthreads();
        // stage A slab rows 0..127, k in [slab*32, slab*32+32) (fp32)
#pragma unroll
        for (int i = 0; i < 4; i++) {
            int idx = tid + i * 256;    // 0..1023 float4 slots
            int row = idx >> 3;         // 0..127
            int kq  = idx & 7;          // 0..7
            float4 v = make_float4(0.f, 0.f, 0.f, 0.f);
            int m = m0 + row;
            if (m < M)
                v = *(const float4*)(A + (size_t)m * 128 + slab * 32 + kq * 4);
            float* p = As + row * AS_STRIDE + kq * 4;
            p[0] = v.x; p[1] = v.y; p[2] = v.z; p[3] = v.w;
        }
        __syncthreads();

#pragma unroll
        for (int kk = 0; kk < 4; kk++) {
            int kc = kk * 8 + c;   // k within slab for this thread
            uint2 a0 = hl_split(As[r0 * AS_STRIDE + kc]);
            uint2 a1 = hl_split(As[(r0 + 8) * AS_STRIDE + kc]);
            uint2 a2 = hl_split(As[r0 * AS_STRIDE + kc + 4]);
            uint2 a3 = hl_split(As[(r0 + 8) * AS_STRIDE + kc + 4]);

            int kg = slab * 32 + kk * 8;   // global k base
#pragma unroll
            for (int nt = 0; nt < 8; nt++) {
                int n = nt * 8 + g;        // local n in half
                uint2 b0 = *(const uint2*)(Ws + n * WHL_STRIDE + 2 * (kg + c));
                uint2 b1 = *(const uint2*)(Ws + n * WHL_STRIDE + 2 * (kg + c + 4));

                mma_tf32(acc[nt], a0.x, a1.x, a2.x, a3.x, b0.y, b1.y);  // hi*lo
                mma_tf32(acc[nt], a0.y, a1.y, a2.y, a3.y, b0.x, b1.x);  // lo*hi
                mma_tf32(acc[nt], a0.x, a1.x, a2.x, a3.x, b0.x, b1.x);  // hi*hi
            }
        }
    }

    // epilogue: bias + optional relu; rows m0+r0, m0+r0+8; cols n0+nt*8+2c(+1)
    int mA = m0 + r0;
    int mB = mA + 8;
#pragma unroll
    for (int nt = 0; nt < 8; nt++) {
        int n = n0 + nt * 8 + 2 * c;
        float bx = bias[n], by = bias[n + 1];
        float2 oA = make_float2(acc[nt][0] + bx, acc[nt][1] + by);
        float2 oB = make_float2(acc[nt][2] + bx, acc[nt][3] + by);
        if (relu) {
            oA.x = fmaxf(oA.x, 0.f); oA.y = fmaxf(oA.y, 0.f);
            oB.x = fmaxf(oB.x, 0.f); oB.y = fmaxf(oB.y, 0.f);
        }
        if (mA < M) *(float2*)(C + (size_t)mA * 128 + n) = oA;
        if (mB < M) *(float2*)(C + (size_t)mB * 128 + n) = oB;
    }
}

// ---------------------------------------------------------------------------
// Warp per dst node: softmax-weighted aggregation of V[src] over CSR edges.
// ---------------------------------------------------------------------------
__device__ __forceinline__ void edge_step(int sj, const float4& q,
                                          float4& acc, float& ssum, int lane)
{
    float4 k = ((const float4*)(g_K + (size_t)sj * 128))[lane];
    float4 v = ((const float4*)(g_V + (size_t)sj * 128))[lane];
    float part = q.x * k.x + q.y * k.y + q.z * k.z + q.w * k.w;
    part += __shfl_xor_sync(0xFFFFFFFFu, part, 1);
    part += __shfl_xor_sync(0xFFFFFFFFu, part, 2);
    part += __shfl_xor_sync(0xFFFFFFFFu, part, 4);
    float p = __expf(part * 0.17677669529663687f);
    acc.x = fmaf(p, v.x, acc.x);
    acc.y = fmaf(p, v.y, acc.y);
    acc.z = fmaf(p, v.z, acc.z);
    acc.w = fmaf(p, v.w, acc.w);
    ssum += p;
}

__global__ __launch_bounds__(256)
void aggregate_kernel(int M)
{
    int w    = (int)(((long long)blockIdx.x * blockDim.x + threadIdx.x) >> 5);
    int lane = threadIdx.x & 31;
    if (w >= M) return;

    int start = g_off[w];
    int end   = g_cur[w];    // == g_off[w+1] after scatter

    float4 q = ((const float4*)(g_Q + (size_t)w * 128))[lane];
    float4 acc = make_float4(0.f, 0.f, 0.f, 0.f);
    float ssum = 0.f;

    int i = start;
    for (; i + 32 <= end; i += 32) {
        int s = g_srcs[i + lane];
#pragma unroll 4
        for (int j = 0; j < 32; j++) {
            int sj = __shfl_sync(0xFFFFFFFFu, s, j);
            edge_step(sj, q, acc, ssum, lane);
        }
    }
    if (i < end) {
        int rem = end - i;
        int s = (lane < rem) ? g_srcs[i + lane] : 0;
        for (int j = 0; j < rem; j++) {
            int sj = __shfl_sync(0xFFFFFFFFu, s, j);
            edge_step(sj, q, acc, ssum, lane);
        }
    }

    float inv = 1.f / (ssum + 1e-8f);
    float4 o = make_float4(acc.x * inv, acc.y * inv, acc.z * inv, acc.w * inv);
    ((float4*)(g_agg + (size_t)w * 128))[lane] = o;
}

// ---------------------------------------------------------------------------
extern "C" void kernel_launch(void* const* d_in, const int* in_sizes, int n_in,
                              void* d_out, int out_size)
{
    const float* x  = (const float*)d_in[0];
    const void*  ei = d_in[1];
    const float* Wq = (const float*)d_in[2];
    const float* bq = (const float*)d_in[3];
    const float* Wk = (const float*)d_in[4];
    const float* bk = (const float*)d_in[5];
    const float* Wv = (const float*)d_in[6];
    const float* bv = (const float*)d_in[7];
    const float* Wo = (const float*)d_in[8];
    const float* bo = (const float*)d_in[9];
    float*       out = (float*)d_out;

    int M = in_sizes[0] / 128;   // nodes
    int E = in_sizes[1] / 2;     // edges

    float *pQ, *pK, *pV, *pAgg;
    cudaGetSymbolAddress((void**)&pQ,   g_Q);
    cudaGetSymbolAddress((void**)&pK,   g_K);
    cudaGetSymbolAddress((void**)&pV,   g_V);
    cudaGetSymbolAddress((void**)&pAgg, g_agg);

    cudaFuncSetAttribute(gemm_tf32_kernel,
                         cudaFuncAttributeMaxDynamicSharedMemorySize, GEMM_SMEM);

    // lazily-created side stream + fork/join events (host resources only;
    // identical launched work every call -> deterministic, graph-capturable)
    static cudaStream_t s2 = 0;
    static cudaEvent_t  evFork = 0, evJoin = 0;
    if (!s2) {
        cudaStreamCreateWithFlags(&s2, cudaStreamNonBlocking);
        cudaEventCreateWithFlags(&evFork, cudaEventDisableTiming);
        cudaEventCreateWithFlags(&evJoin, cudaEventDisableTiming);
    }

    int nb = (M + SCAN_BLK - 1) / SCAN_BLK;   // 49 for M=50000

    // fork: CSR build chain on s2, QKV GEMM on the main (capture) stream
    cudaEventRecord(evFork, 0);
    cudaStreamWaitEvent(s2, evFork, 0);

    detect_kernel<<<1, 32, 0, s2>>>((const unsigned*)ei);
    zero_deg<<<(M + 255) / 256, 256, 0, s2>>>(M);
    hist_kernel<<<(E + 255) / 256, 256, 0, s2>>>(ei, E, M);
    scan_partial<<<nb, SCAN_BLK, 0, s2>>>(M);
    scan_bsums<<<1, MAX_SBLKS, 0, s2>>>(nb);
    scan_add<<<nb + 1, SCAN_BLK, 0, s2>>>(M);
    scatter_kernel<<<(E + 255) / 256, 256, 0, s2>>>(ei, E, M);
    cudaEventRecord(evJoin, s2);

    dim3 gqkv((M + 127) / 128, 6);   // 3 matrices x 2 n-halves
    gemm_tf32_kernel<<<gqkv, 256, GEMM_SMEM>>>(x, M, Wq, Wk, Wv, bq, bk, bv,
                                               pQ, pK, pV, 0);

    // join: aggregate needs both QKV (main) and CSR (s2)
    cudaStreamWaitEvent(0, evJoin, 0);

    long long wt = (long long)M * 32;
    aggregate_kernel<<<(int)((wt + 255) / 256), 256>>>(M);

    dim3 gout((M + 127) / 128, 2);   // 1 matrix x 2 n-halves
    gemm_tf32_kernel<<<gout, 256, GEMM_SMEM>>>(pAgg, M, Wo, Wo, Wo, bo, bo, bo,
                                               out, out, out, 1);
}

// round 12
// speedup vs baseline: 1.2089x; 1.0301x over previous
#include <cuda_runtime.h>
#include <cuda_fp16.h>

// ---------------------------------------------------------------------------
// GAT layer: CSR-gather + tf32 tensor-core GEMM (3-term hi/lo split ~ fp32),
// K/V stored fp16 (halves the edge-gather traffic; 10 mantissa bits keeps
// rel_err ~3e-4, bf16's 8 bits failed at 1.3e-3), two-stream overlap:
//   stream A (legacy): QKV GEMM  (Q fp32, K/V fp16 epilogue)
//   stream B:          CSR build (detect -> zero -> hist -> scan -> scatter)
//   join -> aggregate (warp per dst, fp32 register softmax) -> out GEMM + relu
// ---------------------------------------------------------------------------

#define MAXN 50048
#define MAXE 1600000
#define SCAN_BLK 1024
#define MAX_SBLKS 64

__device__ float  g_Q[MAXN * 128];
__device__ __half g_Kh[MAXN * 128];
__device__ __half g_Vh[MAXN * 128];
__device__ float  g_agg[MAXN * 128];
__device__ int    g_off[MAXN + 1];   // CSR row starts
__device__ int    g_cur[MAXN];       // scatter cursors; == row end after sort
__device__ int    g_srcs[MAXE];      // src ids sorted by dst
__device__ int    g_bsum[MAX_SBLKS]; // per-block sums for scan
__device__ int    g_idx64;           // 1 if edge_index is int64, 0 if int32

__device__ __forceinline__ int load_idx(const void* ei, long long pos, int M) {
    int v;
    if (g_idx64) v = (int)((const long long*)ei)[pos];
    else         v = ((const int*)ei)[pos];
    v = v < 0 ? 0 : (v >= M ? M - 1 : v);   // defensive clamp
    return v;
}

// ---------------------------------------------------------------------------
__global__ void detect_kernel(const unsigned* __restrict__ ei_u32) {
    if (threadIdx.x == 0 && blockIdx.x == 0) {
        int is64 = 1;
        for (int i = 0; i < 128; i++)
            if (ei_u32[2 * i + 1] != 0u) { is64 = 0; break; }
        g_idx64 = is64;
    }
}

__global__ void zero_deg(int M) {
    int t = blockIdx.x * blockDim.x + threadIdx.x;
    if (t < M) g_off[t] = 0;          // reuse g_off as degree counter
}

__global__ void hist_kernel(const void* __restrict__ ei, int E, int M) {
    int t = blockIdx.x * blockDim.x + threadIdx.x;
    if (t >= E) return;
    int dst = load_idx(ei, (long long)E + t, M);
    atomicAdd(&g_off[dst], 1);
}

// ---------------------------------------------------------------------------
// Multi-block exclusive scan of g_off[0..M) (degrees -> offsets).
// ---------------------------------------------------------------------------
__global__ void scan_partial(int M) {
    __shared__ int wsum[32];
    int tid  = threadIdx.x;
    int gi   = blockIdx.x * SCAN_BLK + tid;
    int lane = tid & 31;
    int wid  = tid >> 5;

    int v = (gi < M) ? g_off[gi] : 0;

    int x = v;
#pragma unroll
    for (int o = 1; o < 32; o <<= 1) {
        int y = __shfl_up_sync(0xFFFFFFFFu, x, o);
        if (lane >= o) x += y;
    }
    if (lane == 31) wsum[wid] = x;
    __syncthreads();

    if (wid == 0) {
        int w = wsum[lane];
#pragma unroll
        for (int o = 1; o < 32; o <<= 1) {
            int y = __shfl_up_sync(0xFFFFFFFFu, w, o);
            if (lane >= o) w += y;
        }
        wsum[lane] = w;
    }
    __syncthreads();

    int incl = x + (wid > 0 ? wsum[wid - 1] : 0);
    int excl = incl - v;
    if (gi < M) g_off[gi] = excl;
    if (tid == SCAN_BLK - 1) g_bsum[blockIdx.x] = incl;
}

__global__ void scan_bsums(int nb) {
    __shared__ int s[MAX_SBLKS];
    int lane = threadIdx.x;
    if (lane < MAX_SBLKS) s[lane] = (lane < nb) ? g_bsum[lane] : 0;
    __syncthreads();
    if (lane == 0) {
        int run = 0;
        for (int i = 0; i < nb; i++) { int t = s[i]; s[i] = run; run += t; }
        s[nb] = run;
    }
    __syncthreads();
    if (lane <= nb) g_bsum[lane] = s[lane];
}

__global__ void scan_add(int M) {
    int tid = threadIdx.x;
    int gi  = blockIdx.x * SCAN_BLK + tid;
    if (gi < M) {
        int o = g_off[gi] + g_bsum[blockIdx.x];
        g_off[gi] = o;
        g_cur[gi] = o;
    }
    if (gi == M) {
        int nb = (M + SCAN_BLK - 1) / SCAN_BLK;
        g_off[M] = g_bsum[nb];
    }
}

__global__ void scatter_kernel(const void* __restrict__ ei, int E, int M) {
    int t = blockIdx.x * blockDim.x + threadIdx.x;
    if (t >= E) return;
    int src = load_idx(ei, t, M);
    int dst = load_idx(ei, (long long)E + t, M);
    int pos = atomicAdd(&g_cur[dst], 1);
    g_srcs[pos] = src;
}

// ---------------------------------------------------------------------------
// tf32 tensor-core GEMM, 3-term hi/lo split (~fp32):
//   C tile = A[128 rows, 128k] @ Whalf[64, 128]^T + bias (+relu)
// 256 thr = 8 warps; warp w owns rows [w*16, w*16+16) x 64 cols (8 m16n8 accs).
// W half pre-converted ONCE to interleaved tf32 (hi,lo) uint2 (stride 264:
// conflict-free LDS.64); A fp32 smem (stride 36: conflict-free), cvt in loop.
// blockIdx.y: bit0 = n-half (0/1), bits>=1 = matrix select (QKV fusion).
// fp16_mask bit `mat` set -> C is written as fp16 instead of fp32.
// ---------------------------------------------------------------------------
#define WHL_STRIDE 264
#define AS_STRIDE 36
#define GEMM_SMEM ((64 * WHL_STRIDE + 128 * AS_STRIDE) * 4)

__device__ __forceinline__ unsigned f2tf32(float x) {
    unsigned r;
    asm("cvt.rna.tf32.f32 %0, %1;" : "=r"(r) : "f"(x));
    return r;
}
__device__ __forceinline__ uint2 hl_split(float x) {
    uint2 r;
    r.x = f2tf32(x);
    r.y = f2tf32(x - __uint_as_float(r.x));
    return r;
}

__device__ __forceinline__ void mma_tf32(float* d,
                                         unsigned a0, unsigned a1,
                                         unsigned a2, unsigned a3,
                                         unsigned b0, unsigned b1) {
    asm("mma.sync.aligned.m16n8k8.row.col.f32.tf32.tf32.f32 "
        "{%0,%1,%2,%3}, {%4,%5,%6,%7}, {%8,%9}, {%0,%1,%2,%3};"
        : "+f"(d[0]), "+f"(d[1]), "+f"(d[2]), "+f"(d[3])
        : "r"(a0), "r"(a1), "r"(a2), "r"(a3), "r"(b0), "r"(b1));
}

__global__ __launch_bounds__(256, 2)
void gemm_tf32_kernel(const float* __restrict__ A, int M,
                      const float* __restrict__ Wa, const float* __restrict__ Wb,
                      const float* __restrict__ Wc,
                      const float* __restrict__ ba, const float* __restrict__ bb,
                      const float* __restrict__ bc,
                      void* __restrict__ Ca, void* __restrict__ Cb,
                      void* __restrict__ Cc,
                      int fp16_mask, int relu)
{
    extern __shared__ unsigned smem_u[];
    unsigned* Ws = smem_u;                             // [64][WHL_STRIDE]
    float*    As = (float*)(smem_u + 64 * WHL_STRIDE); // [128][AS_STRIDE]

    int mat  = blockIdx.y >> 1;
    int n0   = (blockIdx.y & 1) * 64;    // n-half offset

    const float* W;
    const float* bias;
    void*        C;
    if (mat == 0)      { W = Wa; bias = ba; C = Ca; }
    else if (mat == 1) { W = Wb; bias = bb; C = Cb; }
    else               { W = Wc; bias = bc; C = Cc; }
    int h16out = (fp16_mask >> mat) & 1;

    int tid  = threadIdx.x;
    int wid  = tid >> 5;
    int lane = tid & 31;
    int g    = lane >> 2;      // group id 0..7
    int c    = lane & 3;       // thread-in-group 0..3
    int m0   = blockIdx.x * 128;

    // stage W half (rows n0..n0+63 of W) as tf32 hi/lo pairs: 8 float4/thread
#pragma unroll
    for (int i = 0; i < 8; i++) {
        int i4  = tid + i * 256;        // 0..2047
        int row = i4 >> 5;              // 0..63  (local n)
        int c4  = (i4 & 31) * 4;        // k: 0..124
        float4 w = *(const float4*)(W + (size_t)(n0 + row) * 128 + c4);
        uint2* p = (uint2*)(Ws + row * WHL_STRIDE + 2 * c4);
        p[0] = hl_split(w.x);
        p[1] = hl_split(w.y);
        p[2] = hl_split(w.z);
        p[3] = hl_split(w.w);
    }

    float acc[8][4];
#pragma unroll
    for (int t = 0; t < 8; t++)
#pragma unroll
        for (int j = 0; j < 4; j++) acc[t][j] = 0.f;

    int r0 = wid * 16 + g;     // warp-local A rows r0, r0+8

    for (int slab = 0; slab < 4; slab++) {
        __syncthreads();
        // stage A slab rows 0..127, k in [slab*32, slab*32+32) (fp32)
#pragma unroll
        for (int i = 0; i < 4; i++) {
            int idx = tid + i * 256;    // 0..1023 float4 slots
            int row = idx >> 3;         // 0..127
            int kq  = idx & 7;          // 0..7
            float4 v = make_float4(0.f, 0.f, 0.f, 0.f);
            int m = m0 + row;
            if (m < M)
                v = *(const float4*)(A + (size_t)m * 128 + slab * 32 + kq * 4);
            float* p = As + row * AS_STRIDE + kq * 4;
            p[0] = v.x; p[1] = v.y; p[2] = v.z; p[3] = v.w;
        }
        __syncthreads();

#pragma unroll
        for (int kk = 0; kk < 4; kk++) {
            int kc = kk * 8 + c;   // k within slab for this thread
            uint2 a0 = hl_split(As[r0 * AS_STRIDE + kc]);
            uint2 a1 = hl_split(As[(r0 + 8) * AS_STRIDE + kc]);
            uint2 a2 = hl_split(As[r0 * AS_STRIDE + kc + 4]);
            uint2 a3 = hl_split(As[(r0 + 8) * AS_STRIDE + kc + 4]);

            int kg = slab * 32 + kk * 8;   // global k base
#pragma unroll
            for (int nt = 0; nt < 8; nt++) {
                int n = nt * 8 + g;        // local n in half
                uint2 b0 = *(const uint2*)(Ws + n * WHL_STRIDE + 2 * (kg + c));
                uint2 b1 = *(const uint2*)(Ws + n * WHL_STRIDE + 2 * (kg + c + 4));

                mma_tf32(acc[nt], a0.x, a1.x, a2.x, a3.x, b0.y, b1.y);  // hi*lo
                mma_tf32(acc[nt], a0.y, a1.y, a2.y, a3.y, b0.x, b1.x);  // lo*hi
                mma_tf32(acc[nt], a0.x, a1.x, a2.x, a3.x, b0.x, b1.x);  // hi*hi
            }
        }
    }

    // epilogue: bias + optional relu; rows m0+r0, m0+r0+8; cols n0+nt*8+2c(+1)
    int mA = m0 + r0;
    int mB = mA + 8;
#pragma unroll
    for (int nt = 0; nt < 8; nt++) {
        int n = n0 + nt * 8 + 2 * c;
        float bx = bias[n], by = bias[n + 1];
        float2 oA = make_float2(acc[nt][0] + bx, acc[nt][1] + by);
        float2 oB = make_float2(acc[nt][2] + bx, acc[nt][3] + by);
        if (relu) {
            oA.x = fmaxf(oA.x, 0.f); oA.y = fmaxf(oA.y, 0.f);
            oB.x = fmaxf(oB.x, 0.f); oB.y = fmaxf(oB.y, 0.f);
        }
        if (h16out) {
            __half* Ch = (__half*)C;
            if (mA < M) *(__half2*)(Ch + (size_t)mA * 128 + n) =
                __floats2half2_rn(oA.x, oA.y);
            if (mB < M) *(__half2*)(Ch + (size_t)mB * 128 + n) =
                __floats2half2_rn(oB.x, oB.y);
        } else {
            float* Cf = (float*)C;
            if (mA < M) *(float2*)(Cf + (size_t)mA * 128 + n) = oA;
            if (mB < M) *(float2*)(Cf + (size_t)mB * 128 + n) = oB;
        }
    }
}

// ---------------------------------------------------------------------------
// Warp per dst node: softmax-weighted aggregation of V[src] over CSR edges.
// K/V rows are fp16 (256B each): lane l loads uint2 = elements 4l..4l+3.
// All accumulation in fp32.
// ---------------------------------------------------------------------------
__device__ __forceinline__ void edge_step(int sj, const float4& q,
                                          float4& acc, float& ssum, int lane)
{
    uint2 kr = ((const uint2*)(g_Kh + (size_t)sj * 128))[lane];
    uint2 vr = ((const uint2*)(g_Vh + (size_t)sj * 128))[lane];
    float2 k0 = __half22float2(*(__half2*)&kr.x);
    float2 k1 = __half22float2(*(__half2*)&kr.y);
    float part = q.x * k0.x + q.y * k0.y + q.z * k1.x + q.w * k1.y;
    part += __shfl_xor_sync(0xFFFFFFFFu, part, 1);
    part += __shfl_xor_sync(0xFFFFFFFFu, part, 2);
    part += __shfl_xor_sync(0xFFFFFFFFu, part, 4);
    float p = __expf(part * 0.17677669529663687f);
    float2 v0 = __half22float2(*(__half2*)&vr.x);
    float2 v1 = __half22float2(*(__half2*)&vr.y);
    acc.x = fmaf(p, v0.x, acc.x);
    acc.y = fmaf(p, v0.y, acc.y);
    acc.z = fmaf(p, v1.x, acc.z);
    acc.w = fmaf(p, v1.y, acc.w);
    ssum += p;
}

__global__ __launch_bounds__(256)
void aggregate_kernel(int M)
{
    int w    = (int)(((long long)blockIdx.x * blockDim.x + threadIdx.x) >> 5);
    int lane = threadIdx.x & 31;
    if (w >= M) return;

    int start = g_off[w];
    int end   = g_cur[w];    // == g_off[w+1] after scatter

    float4 q = ((const float4*)(g_Q + (size_t)w * 128))[lane];
    float4 acc = make_float4(0.f, 0.f, 0.f, 0.f);
    float ssum = 0.f;

    int i = start;
    for (; i + 32 <= end; i += 32) {
        int s = g_srcs[i + lane];
#pragma unroll 4
        for (int j = 0; j < 32; j++) {
            int sj = __shfl_sync(0xFFFFFFFFu, s, j);
            edge_step(sj, q, acc, ssum, lane);
        }
    }
    if (i < end) {
        int rem = end - i;
        int s = (lane < rem) ? g_srcs[i + lane] : 0;
        for (int j = 0; j < rem; j++) {
            int sj = __shfl_sync(0xFFFFFFFFu, s, j);
            edge_step(sj, q, acc, ssum, lane);
        }
    }

    float inv = 1.f / (ssum + 1e-8f);
    float4 o = make_float4(acc.x * inv, acc.y * inv, acc.z * inv, acc.w * inv);
    ((float4*)(g_agg + (size_t)w * 128))[lane] = o;
}

// ---------------------------------------------------------------------------
extern "C" void kernel_launch(void* const* d_in, const int* in_sizes, int n_in,
                              void* d_out, int out_size)
{
    const float* x  = (const float*)d_in[0];
    const void*  ei = d_in[1];
    const float* Wq = (const float*)d_in[2];
    const float* bq = (const float*)d_in[3];
    const float* Wk = (const float*)d_in[4];
    const float* bk = (const float*)d_in[5];
    const float* Wv = (const float*)d_in[6];
    const float* bv = (const float*)d_in[7];
    const float* Wo = (const float*)d_in[8];
    const float* bo = (const float*)d_in[9];
    float*       out = (float*)d_out;

    int M = in_sizes[0] / 128;   // nodes
    int E = in_sizes[1] / 2;     // edges

    float *pQ, *pAgg;
    __half *pKh, *pVh;
    cudaGetSymbolAddress((void**)&pQ,   g_Q);
    cudaGetSymbolAddress((void**)&pKh,  g_Kh);
    cudaGetSymbolAddress((void**)&pVh,  g_Vh);
    cudaGetSymbolAddress((void**)&pAgg, g_agg);

    cudaFuncSetAttribute(gemm_tf32_kernel,
                         cudaFuncAttributeMaxDynamicSharedMemorySize, GEMM_SMEM);

    // lazily-created side stream + fork/join events (host resources only;
    // identical launched work every call -> deterministic, graph-capturable)
    static cudaStream_t s2 = 0;
    static cudaEvent_t  evFork = 0, evJoin = 0;
    if (!s2) {
        cudaStreamCreateWithFlags(&s2, cudaStreamNonBlocking);
        cudaEventCreateWithFlags(&evFork, cudaEventDisableTiming);
        cudaEventCreateWithFlags(&evJoin, cudaEventDisableTiming);
    }

    int nb = (M + SCAN_BLK - 1) / SCAN_BLK;   // 49 for M=50000

    // fork: CSR build chain on s2, QKV GEMM on the main (capture) stream
    cudaEventRecord(evFork, 0);
    cudaStreamWaitEvent(s2, evFork, 0);

    detect_kernel<<<1, 32, 0, s2>>>((const unsigned*)ei);
    zero_deg<<<(M + 255) / 256, 256, 0, s2>>>(M);
    hist_kernel<<<(E + 255) / 256, 256, 0, s2>>>(ei, E, M);
    scan_partial<<<nb, SCAN_BLK, 0, s2>>>(M);
    scan_bsums<<<1, MAX_SBLKS, 0, s2>>>(nb);
    scan_add<<<nb + 1, SCAN_BLK, 0, s2>>>(M);
    scatter_kernel<<<(E + 255) / 256, 256, 0, s2>>>(ei, E, M);
    cudaEventRecord(evJoin, s2);

    dim3 gqkv((M + 127) / 128, 6);   // 3 matrices x 2 n-halves
    gemm_tf32_kernel<<<gqkv, 256, GEMM_SMEM>>>(x, M, Wq, Wk, Wv, bq, bk, bv,
                                               pQ, pKh, pVh,
                                               /*fp16_mask=*/0b110, 0);

    // join: aggregate needs both QKV (main) and CSR (s2)
    cudaStreamWaitEvent(0, evJoin, 0);

    long long wt = (long long)M * 32;
    aggregate_kernel<<<(int)((wt + 255) / 256), 256>>>(M);

    dim3 gout((M + 127) / 128, 2);   // 1 matrix x 2 n-halves
    gemm_tf32_kernel<<<gout, 256, GEMM_SMEM>>>(pAgg, M, Wo, Wo, Wo, bo, bo, bo,
                                               out, out, out,
                                               /*fp16_mask=*/0, 1);
}

// round 13
// speedup vs baseline: 1.4297x; 1.1827x over previous
#include <cuda_runtime.h>
#include <cuda_fp16.h>

// ---------------------------------------------------------------------------
// GAT layer: CSR-gather + fp16 tensor-core GEMM (hi/lo split, m16n8k16,
// W pre-scaled x16 to keep lo parts out of subnormal range, fp32 accum,
// epilogue x1/16), K/V stored fp16, two-stream overlap:
//   stream A (legacy): QKV GEMM  (Q fp32, K/V fp16 epilogue)
//   stream B:          CSR build (detect -> zero -> hist -> scan -> scatter)
//   join -> aggregate (warp per dst, fp32 register softmax) -> out GEMM + relu
// ---------------------------------------------------------------------------

#define MAXN 50048
#define MAXE 1600000
#define SCAN_BLK 1024
#define MAX_SBLKS 64

__device__ float  g_Q[MAXN * 128];
__device__ __half g_Kh[MAXN * 128];
__device__ __half g_Vh[MAXN * 128];
__device__ float  g_agg[MAXN * 128];
__device__ int    g_off[MAXN + 1];   // CSR row starts
__device__ int    g_cur[MAXN];       // scatter cursors; == row end after sort
__device__ int    g_srcs[MAXE];      // src ids sorted by dst
__device__ int    g_bsum[MAX_SBLKS]; // per-block sums for scan
__device__ int    g_idx64;           // 1 if edge_index is int64, 0 if int32

__device__ __forceinline__ int load_idx(const void* ei, long long pos, int M) {
    int v;
    if (g_idx64) v = (int)((const long long*)ei)[pos];
    else         v = ((const int*)ei)[pos];
    v = v < 0 ? 0 : (v >= M ? M - 1 : v);   // defensive clamp
    return v;
}

// ---------------------------------------------------------------------------
__global__ void detect_kernel(const unsigned* __restrict__ ei_u32) {
    if (threadIdx.x == 0 && blockIdx.x == 0) {
        int is64 = 1;
        for (int i = 0; i < 128; i++)
            if (ei_u32[2 * i + 1] != 0u) { is64 = 0; break; }
        g_idx64 = is64;
    }
}

__global__ void zero_deg(int M) {
    int t = blockIdx.x * blockDim.x + threadIdx.x;
    if (t < M) g_off[t] = 0;          // reuse g_off as degree counter
}

__global__ void hist_kernel(const void* __restrict__ ei, int E, int M) {
    int t = blockIdx.x * blockDim.x + threadIdx.x;
    if (t >= E) return;
    int dst = load_idx(ei, (long long)E + t, M);
    atomicAdd(&g_off[dst], 1);
}

// ---------------------------------------------------------------------------
// Multi-block exclusive scan of g_off[0..M) (degrees -> offsets).
// ---------------------------------------------------------------------------
__global__ void scan_partial(int M) {
    __shared__ int wsum[32];
    int tid  = threadIdx.x;
    int gi   = blockIdx.x * SCAN_BLK + tid;
    int lane = tid & 31;
    int wid  = tid >> 5;

    int v = (gi < M) ? g_off[gi] : 0;

    int x = v;
#pragma unroll
    for (int o = 1; o < 32; o <<= 1) {
        int y = __shfl_up_sync(0xFFFFFFFFu, x, o);
        if (lane >= o) x += y;
    }
    if (lane == 31) wsum[wid] = x;
    __syncthreads();

    if (wid == 0) {
        int w = wsum[lane];
#pragma unroll
        for (int o = 1; o < 32; o <<= 1) {
            int y = __shfl_up_sync(0xFFFFFFFFu, w, o);
            if (lane >= o) w += y;
        }
        wsum[lane] = w;
    }
    __syncthreads();

    int incl = x + (wid > 0 ? wsum[wid - 1] : 0);
    int excl = incl - v;
    if (gi < M) g_off[gi] = excl;
    if (tid == SCAN_BLK - 1) g_bsum[blockIdx.x] = incl;
}

__global__ void scan_bsums(int nb) {
    __shared__ int s[MAX_SBLKS];
    int lane = threadIdx.x;
    if (lane < MAX_SBLKS) s[lane] = (lane < nb) ? g_bsum[lane] : 0;
    __syncthreads();
    if (lane == 0) {
        int run = 0;
        for (int i = 0; i < nb; i++) { int t = s[i]; s[i] = run; run += t; }
        s[nb] = run;
    }
    __syncthreads();
    if (lane <= nb) g_bsum[lane] = s[lane];
}

__global__ void scan_add(int M) {
    int tid = threadIdx.x;
    int gi  = blockIdx.x * SCAN_BLK + tid;
    if (gi < M) {
        int o = g_off[gi] + g_bsum[blockIdx.x];
        g_off[gi] = o;
        g_cur[gi] = o;
    }
    if (gi == M) {
        int nb = (M + SCAN_BLK - 1) / SCAN_BLK;
        g_off[M] = g_bsum[nb];
    }
}

__global__ void scatter_kernel(const void* __restrict__ ei, int E, int M) {
    int t = blockIdx.x * blockDim.x + threadIdx.x;
    if (t >= E) return;
    int src = load_idx(ei, t, M);
    int dst = load_idx(ei, (long long)E + t, M);
    int pos = atomicAdd(&g_cur[dst], 1);
    g_srcs[pos] = src;
}

// ---------------------------------------------------------------------------
// fp16 tensor-core GEMM, hi/lo split (~22-bit mantissa):
//   C tile = A[128 rows, 128k] @ Whalf[64, 128]^T + bias (+relu)
// 256 thr = 8 warps; warp w owns rows [w*16, w*16+16) x 64 cols (8 m16n8 accs).
// W half pre-scaled x16 and converted ONCE to {hi2, lo2} uint2 per k-pair
// (stride 136 words: 8B-bank = 4g+c, conflict-free LDS.64). A fp32 smem
// (stride 36), converted to fp16 hi/lo fragments in-loop.
// mma.m16n8k16.f16 x3 terms (hi*hi + hi*lo + lo*hi), fp32 accum, epi x1/16.
// blockIdx.y: bit0 = n-half (0/1), bits>=1 = matrix select (QKV fusion).
// fp16_mask bit `mat` set -> C is written as fp16 instead of fp32.
// ---------------------------------------------------------------------------
#define WHL_STRIDE 136
#define AS_STRIDE 36
#define GEMM_SMEM ((64 * WHL_STRIDE + 128 * AS_STRIDE) * 4)

// pack two floats into {half2 hi, half2 lo}
__device__ __forceinline__ uint2 h2_split2(float x, float y) {
    __half hx = __float2half_rn(x);
    __half hy = __float2half_rn(y);
    __half lx = __float2half_rn(x - __half2float(hx));
    __half ly = __float2half_rn(y - __half2float(hy));
    __half2 h = __halves2half2(hx, hy);
    __half2 l = __halves2half2(lx, ly);
    uint2 r;
    r.x = *(unsigned*)&h;
    r.y = *(unsigned*)&l;
    return r;
}

__device__ __forceinline__ void mma_f16(float* d,
                                        unsigned a0, unsigned a1,
                                        unsigned a2, unsigned a3,
                                        unsigned b0, unsigned b1) {
    asm("mma.sync.aligned.m16n8k16.row.col.f32.f16.f16.f32 "
        "{%0,%1,%2,%3}, {%4,%5,%6,%7}, {%8,%9}, {%0,%1,%2,%3};"
        : "+f"(d[0]), "+f"(d[1]), "+f"(d[2]), "+f"(d[3])
        : "r"(a0), "r"(a1), "r"(a2), "r"(a3), "r"(b0), "r"(b1));
}

__global__ __launch_bounds__(256, 2)
void gemm_f16_kernel(const float* __restrict__ A, int M,
                     const float* __restrict__ Wa, const float* __restrict__ Wb,
                     const float* __restrict__ Wc,
                     const float* __restrict__ ba, const float* __restrict__ bb,
                     const float* __restrict__ bc,
                     void* __restrict__ Ca, void* __restrict__ Cb,
                     void* __restrict__ Cc,
                     int fp16_mask, int relu)
{
    extern __shared__ unsigned smem_u[];
    unsigned* Ws = smem_u;                             // [64][WHL_STRIDE]
    float*    As = (float*)(smem_u + 64 * WHL_STRIDE); // [128][AS_STRIDE]

    int mat  = blockIdx.y >> 1;
    int n0   = (blockIdx.y & 1) * 64;    // n-half offset

    const float* W;
    const float* bias;
    void*        C;
    if (mat == 0)      { W = Wa; bias = ba; C = Ca; }
    else if (mat == 1) { W = Wb; bias = bb; C = Cb; }
    else               { W = Wc; bias = bc; C = Cc; }
    int h16out = (fp16_mask >> mat) & 1;

    int tid  = threadIdx.x;
    int wid  = tid >> 5;
    int lane = tid & 31;
    int g    = lane >> 2;      // group id 0..7
    int c    = lane & 3;       // thread-in-group 0..3
    int m0   = blockIdx.x * 128;

    // stage W half (rows n0..n0+63), x16 scaled, as {hi2,lo2} per k-pair
#pragma unroll
    for (int i = 0; i < 8; i++) {
        int i4  = tid + i * 256;        // 0..2047
        int row = i4 >> 5;              // 0..63  (local n)
        int c4  = (i4 & 31) * 4;        // k: 0..124
        float4 w = *(const float4*)(W + (size_t)(n0 + row) * 128 + c4);
        uint2* p = (uint2*)(Ws + row * WHL_STRIDE) + (c4 >> 1);
        p[0] = h2_split2(w.x * 16.f, w.y * 16.f);
        p[1] = h2_split2(w.z * 16.f, w.w * 16.f);
    }

    float acc[8][4];
#pragma unroll
    for (int t = 0; t < 8; t++)
#pragma unroll
        for (int j = 0; j < 4; j++) acc[t][j] = 0.f;

    int r0 = wid * 16 + g;     // warp-local A rows r0, r0+8

    for (int slab = 0; slab < 4; slab++) {
        __syncthreads();
        // stage A slab rows 0..127, k in [slab*32, slab*32+32) (fp32)
#pragma unroll
        for (int i = 0; i < 4; i++) {
            int idx = tid + i * 256;    // 0..1023 float4 slots
            int row = idx >> 3;         // 0..127
            int kq  = idx & 7;          // 0..7
            float4 v = make_float4(0.f, 0.f, 0.f, 0.f);
            int m = m0 + row;
            if (m < M)
                v = *(const float4*)(A + (size_t)m * 128 + slab * 32 + kq * 4);
            float* p = As + row * AS_STRIDE + kq * 4;
            p[0] = v.x; p[1] = v.y; p[2] = v.z; p[3] = v.w;
        }
        __syncthreads();

#pragma unroll
        for (int kk = 0; kk < 2; kk++) {           // two k16-steps per slab
            int kl = kk * 16;                      // k base within slab
            // A fragment: rows r0,r0+8; k pairs (kl+2c, +1) and (kl+8+2c, +1)
            uint2 A0 = h2_split2(As[r0 * AS_STRIDE + kl + 2 * c],
                                 As[r0 * AS_STRIDE + kl + 2 * c + 1]);
            uint2 A1 = h2_split2(As[(r0 + 8) * AS_STRIDE + kl + 2 * c],
                                 As[(r0 + 8) * AS_STRIDE + kl + 2 * c + 1]);
            uint2 A2 = h2_split2(As[r0 * AS_STRIDE + kl + 8 + 2 * c],
                                 As[r0 * AS_STRIDE + kl + 8 + 2 * c + 1]);
            uint2 A3 = h2_split2(As[(r0 + 8) * AS_STRIDE + kl + 8 + 2 * c],
                                 As[(r0 + 8) * AS_STRIDE + kl + 8 + 2 * c + 1]);

            int kp0 = slab * 16 + kk * 8 + c;      // global k-pair for b0
#pragma unroll
            for (int nt = 0; nt < 8; nt++) {
                int n = nt * 8 + g;                // local n in half
                uint2 B0 = *((const uint2*)(Ws + n * WHL_STRIDE) + kp0);
                uint2 B1 = *((const uint2*)(Ws + n * WHL_STRIDE) + kp0 + 4);

                mma_f16(acc[nt], A0.x, A1.x, A2.x, A3.x, B0.y, B1.y);  // hi*lo
                mma_f16(acc[nt], A0.y, A1.y, A2.y, A3.y, B0.x, B1.x);  // lo*hi
                mma_f16(acc[nt], A0.x, A1.x, A2.x, A3.x, B0.x, B1.x);  // hi*hi
            }
        }
    }

    // epilogue: x1/16 (undo W scaling) + bias + optional relu
    int mA = m0 + r0;
    int mB = mA + 8;
#pragma unroll
    for (int nt = 0; nt < 8; nt++) {
        int n = n0 + nt * 8 + 2 * c;
        float bx = bias[n], by = bias[n + 1];
        float2 oA = make_float2(fmaf(acc[nt][0], 0.0625f, bx),
                                fmaf(acc[nt][1], 0.0625f, by));
        float2 oB = make_float2(fmaf(acc[nt][2], 0.0625f, bx),
                                fmaf(acc[nt][3], 0.0625f, by));
        if (relu) {
            oA.x = fmaxf(oA.x, 0.f); oA.y = fmaxf(oA.y, 0.f);
            oB.x = fmaxf(oB.x, 0.f); oB.y = fmaxf(oB.y, 0.f);
        }
        if (h16out) {
            __half* Ch = (__half*)C;
            if (mA < M) *(__half2*)(Ch + (size_t)mA * 128 + n) =
                __floats2half2_rn(oA.x, oA.y);
            if (mB < M) *(__half2*)(Ch + (size_t)mB * 128 + n) =
                __floats2half2_rn(oB.x, oB.y);
        } else {
            float* Cf = (float*)C;
            if (mA < M) *(float2*)(Cf + (size_t)mA * 128 + n) = oA;
            if (mB < M) *(float2*)(Cf + (size_t)mB * 128 + n) = oB;
        }
    }
}

// ---------------------------------------------------------------------------
// Warp per dst node: softmax-weighted aggregation of V[src] over CSR edges.
// K/V rows are fp16 (256B each): lane l loads uint2 = elements 4l..4l+3.
// All accumulation in fp32.
// ---------------------------------------------------------------------------
__device__ __forceinline__ void edge_step(int sj, const float4& q,
                                          float4& acc, float& ssum, int lane)
{
    uint2 kr = ((const uint2*)(g_Kh + (size_t)sj * 128))[lane];
    uint2 vr = ((const uint2*)(g_Vh + (size_t)sj * 128))[lane];
    float2 k0 = __half22float2(*(__half2*)&kr.x);
    float2 k1 = __half22float2(*(__half2*)&kr.y);
    float part = q.x * k0.x + q.y * k0.y + q.z * k1.x + q.w * k1.y;
    part += __shfl_xor_sync(0xFFFFFFFFu, part, 1);
    part += __shfl_xor_sync(0xFFFFFFFFu, part, 2);
    part += __shfl_xor_sync(0xFFFFFFFFu, part, 4);
    float p = __expf(part * 0.17677669529663687f);
    float2 v0 = __half22float2(*(__half2*)&vr.x);
    float2 v1 = __half22float2(*(__half2*)&vr.y);
    acc.x = fmaf(p, v0.x, acc.x);
    acc.y = fmaf(p, v0.y, acc.y);
    acc.z = fmaf(p, v1.x, acc.z);
    acc.w = fmaf(p, v1.y, acc.w);
    ssum += p;
}

__global__ __launch_bounds__(256)
void aggregate_kernel(int M)
{
    int w    = (int)(((long long)blockIdx.x * blockDim.x + threadIdx.x) >> 5);
    int lane = threadIdx.x & 31;
    if (w >= M) return;

    int start = g_off[w];
    int end   = g_cur[w];    // == g_off[w+1] after scatter

    float4 q = ((const float4*)(g_Q + (size_t)w * 128))[lane];
    float4 acc = make_float4(0.f, 0.f, 0.f, 0.f);
    float ssum = 0.f;

    int i = start;
    for (; i + 32 <= end; i += 32) {
        int s = g_srcs[i + lane];
#pragma unroll 4
        for (int j = 0; j < 32; j++) {
            int sj = __shfl_sync(0xFFFFFFFFu, s, j);
            edge_step(sj, q, acc, ssum, lane);
        }
    }
    if (i < end) {
        int rem = end - i;
        int s = (lane < rem) ? g_srcs[i + lane] : 0;
        for (int j = 0; j < rem; j++) {
            int sj = __shfl_sync(0xFFFFFFFFu, s, j);
            edge_step(sj, q, acc, ssum, lane);
        }
    }

    float inv = 1.f / (ssum + 1e-8f);
    float4 o = make_float4(acc.x * inv, acc.y * inv, acc.z * inv, acc.w * inv);
    ((float4*)(g_agg + (size_t)w * 128))[lane] = o;
}

// ---------------------------------------------------------------------------
extern "C" void kernel_launch(void* const* d_in, const int* in_sizes, int n_in,
                              void* d_out, int out_size)
{
    const float* x  = (const float*)d_in[0];
    const void*  ei = d_in[1];
    const float* Wq = (const float*)d_in[2];
    const float* bq = (const float*)d_in[3];
    const float* Wk = (const float*)d_in[4];
    const float* bk = (const float*)d_in[5];
    const float* Wv = (const float*)d_in[6];
    const float* bv = (const float*)d_in[7];
    const float* Wo = (const float*)d_in[8];
    const float* bo = (const float*)d_in[9];
    float*       out = (float*)d_out;

    int M = in_sizes[0] / 128;   // nodes
    int E = in_sizes[1] / 2;     // edges

    float *pQ, *pAgg;
    __half *pKh, *pVh;
    cudaGetSymbolAddress((void**)&pQ,   g_Q);
    cudaGetSymbolAddress((void**)&pKh,  g_Kh);
    cudaGetSymbolAddress((void**)&pVh,  g_Vh);
    cudaGetSymbolAddress((void**)&pAgg, g_agg);

    cudaFuncSetAttribute(gemm_f16_kernel,
                         cudaFuncAttributeMaxDynamicSharedMemorySize, GEMM_SMEM);

    // lazily-created side stream + fork/join events (host resources only;
    // identical launched work every call -> deterministic, graph-capturable)
    static cudaStream_t s2 = 0;
    static cudaEvent_t  evFork = 0, evJoin = 0;
    if (!s2) {
        cudaStreamCreateWithFlags(&s2, cudaStreamNonBlocking);
        cudaEventCreateWithFlags(&evFork, cudaEventDisableTiming);
        cudaEventCreateWithFlags(&evJoin, cudaEventDisableTiming);
    }

    int nb = (M + SCAN_BLK - 1) / SCAN_BLK;   // 49 for M=50000

    // fork: CSR build chain on s2, QKV GEMM on the main (capture) stream
    cudaEventRecord(evFork, 0);
    cudaStreamWaitEvent(s2, evFork, 0);

    detect_kernel<<<1, 32, 0, s2>>>((const unsigned*)ei);
    zero_deg<<<(M + 255) / 256, 256, 0, s2>>>(M);
    hist_kernel<<<(E + 255) / 256, 256, 0, s2>>>(ei, E, M);
    scan_partial<<<nb, SCAN_BLK, 0, s2>>>(M);
    scan_bsums<<<1, MAX_SBLKS, 0, s2>>>(nb);
    scan_add<<<nb + 1, SCAN_BLK, 0, s2>>>(M);
    scatter_kernel<<<(E + 255) / 256, 256, 0, s2>>>(ei, E, M);
    cudaEventRecord(evJoin, s2);

    dim3 gqkv((M + 127) / 128, 6);   // 3 matrices x 2 n-halves
    gemm_f16_kernel<<<gqkv, 256, GEMM_SMEM>>>(x, M, Wq, Wk, Wv, bq, bk, bv,
                                              pQ, pKh, pVh,
                                              /*fp16_mask=*/0b110, 0);

    // join: aggregate needs both QKV (main) and CSR (s2)
    cudaStreamWaitEvent(0, evJoin, 0);

    long long wt = (long long)M * 32;
    aggregate_kernel<<<(int)((wt + 255) / 256), 256>>>(M);

    dim3 gout((M + 127) / 128, 2);   // 1 matrix x 2 n-halves
    gemm_f16_kernel<<<gout, 256, GEMM_SMEM>>>(pAgg, M, Wo, Wo, Wo, bo, bo, bo,
                                              out, out, out,
                                              /*fp16_mask=*/0, 1);
}